// round 15
// baseline (speedup 1.0000x reference)
#include <cuda_runtime.h>
#include <cuda_fp16.h>
#include <cstdint>

#define D 128
#define MAXN 65536
#define MAXE 1048576
#define NLAYER 5

// ---------------- static scratch ----------------
__device__ float    g_h[(size_t)MAXN * D];
__device__ float    g_h2[(size_t)MAXN * D];
__device__ __half   g_ah[(size_t)MAXN * D];
__device__ __half   g_al[(size_t)MAXN * D];
__device__ __half   g_hh[(size_t)MAXN * 2 * D];
__device__ __half   g_hl[(size_t)MAXN * 2 * D];
__device__ int      g_deg[MAXN];
__device__ int      g_rowptr[MAXN + 1];
__device__ int      g_cursor[MAXN];
__device__ uint32_t g_pack[MAXE];
__device__ int      g_bsum[256];
__device__ int      g_flag1[256];
__device__ int      g_flag2[256];
__device__ float    g_bnstat[2][256];
__device__ __half   g_w1h[NLAYER * 256 * 128];
__device__ __half   g_w1l[NLAYER * 256 * 128];
__device__ __half   g_w2h[NLAYER * 128 * 256];
__device__ __half   g_w2l[NLAYER * 128 * 256];

// ---------------- fused init: edge count | atom encoder | weight prep ------
__global__ void __launch_bounds__(256)
k_init(const int* __restrict__ ei,
       const int* __restrict__ x,
       const float* __restrict__ ae1,
       const float* __restrict__ ae2,
       const float* __restrict__ W1,
       const float* __restrict__ W2,
       int N, int E, int nbE, int nbAtom) {
    int b = blockIdx.x;
    if (b < nbE) {
        int e = b * 256 + threadIdx.x;
        if (e < E) atomicAdd(&g_deg[ei[E + e]], 1);
    } else if (b < nbE + nbAtom) {
        int idx = (b - nbE) * 256 + threadIdx.x;
        if (idx < N * D) {
            int n = idx >> 7, d = idx & (D - 1);
            g_h[idx] = ae1[x[2 * n] * D + d] + ae2[x[2 * n + 1] * D + d];
        }
    } else {
        int idx = (b - nbE - nbAtom) * 256 + threadIdx.x;
        if (idx < NLAYER * 256 * 128) {
            int l = idx >> 15;
            int r = idx & 32767;
            {
                int n = r >> 7, k = r & 127;
                float v = W1[(size_t)l * 32768 + (size_t)k * 256 + n];
                __half h = __float2half_rn(v);
                g_w1h[idx] = h;
                g_w1l[idx] = __float2half_rn(v - __half2float(h));
            }
            {
                int n = r >> 8, k = r & 255;
                float v = W2[(size_t)l * 32768 + (size_t)k * 128 + n];
                __half h = __float2half_rn(v);
                g_w2h[idx] = h;
                g_w2l[idx] = __float2half_rn(v - __half2float(h));
            }
        }
    }
}

// ---------------- fused CSR: scan (decoupled lookback) + packed fill -------
__global__ void __launch_bounds__(256)
k_scanfill(const int* __restrict__ ei, const int* __restrict__ ea,
           int N, int E) {
    int b = blockIdx.x, tid = threadIdx.x;
    int nb = gridDim.x;
    __shared__ int s[256];
    __shared__ int spre[256];

    int i = b * 256 + tid;
    int v = (i < N) ? g_deg[i] : 0;
    s[tid] = v;
    __syncthreads();
    #pragma unroll
    for (int off = 1; off < 256; off <<= 1) {
        int t = (tid >= off) ? s[tid - off] : 0;
        __syncthreads();
        s[tid] += t;
        __syncthreads();
    }
    if (tid == 0) {
        g_bsum[b] = s[255];
        __threadfence();
        atomicExch(&g_flag1[b], 1);
    }

    int part = 0;
    if (tid < b) {
        while (atomicAdd(&g_flag1[tid], 0) == 0) {}
        part = atomicAdd(&g_bsum[tid], 0);
    }
    spre[tid] = part;
    __syncthreads();
    #pragma unroll
    for (int off = 128; off > 0; off >>= 1) {
        if (tid < off) spre[tid] += spre[tid + off];
        __syncthreads();
    }
    int prefix = spre[0];

    if (i < N) {
        int r = prefix + s[tid] - v;
        g_rowptr[i] = r;
        g_cursor[i] = r;
    }
    if (i == 0) g_rowptr[N] = E;
    __threadfence();
    __syncthreads();
    if (tid == 0) atomicExch(&g_flag2[b], 1);

    if (tid < nb) {
        while (atomicAdd(&g_flag2[tid], 0) == 0) {}
    }
    __syncthreads();
    __threadfence();

    for (int e = b * 256 + tid; e < E; e += nb * 256) {
        int dst = ei[E + e];
        int src = ei[e];
        uint32_t code = (uint32_t)(ea[2 * e] * 4 + ea[2 * e + 1]);
        int pos = atomicAdd(&g_cursor[dst], 1);
        g_pack[pos] = (uint32_t)src | (code << 27);
    }
}

// ---------------- aggregation (identical to R9) ----------------
__global__ void __launch_bounds__(256)
k_aggregate(const float* __restrict__ be1,
            const float* __restrict__ be2,
            const float* __restrict__ srcfeat,
            const float* __restrict__ bnstat_prev,
            float* __restrict__ bnstat_cur,
            const float* __restrict__ gammaP,
            const float* __restrict__ betaP,
            int N, int doBN) {
    __shared__ float s_bt[28 * 128];
    for (int idx = threadIdx.x; idx < 28 * 128; idx += 256) {
        int c = idx >> 7, d = idx & 127;
        s_bt[idx] = be1[(c >> 2) * 128 + d] + be2[(c & 3) * 128 + d];
    }
    if (blockIdx.x == 0 && threadIdx.x < 256) bnstat_cur[threadIdx.x] = 0.f;
    __syncthreads();

    int gw = (blockIdx.x * blockDim.x + threadIdx.x) >> 5;
    int lane = threadIdx.x & 31;
    if (gw >= N) return;
    int n = gw;

    float4 scale = make_float4(1.f, 1.f, 1.f, 1.f);
    float4 shift = make_float4(0.f, 0.f, 0.f, 0.f);
    if (doBN) {
        float invN = 1.0f / (float)N;
        #pragma unroll
        for (int q = 0; q < 4; q++) {
            int c = lane * 4 + q;
            float mu = bnstat_prev[c] * invN;
            float var = bnstat_prev[128 + c] * invN - mu * mu;
            float istd = rsqrtf(var + 1e-5f);
            float sc = istd * gammaP[c];
            float sh = betaP[c] - mu * sc;
            ((float*)&scale)[q] = sc;
            ((float*)&shift)[q] = sh;
        }
    }

    const float4* h4 = (const float4*)srcfeat;

    float4 hv = h4[(size_t)n * 32 + lane];
    float4 acc;
    if (doBN) {
        acc.x = fmaxf(fmaf(hv.x, scale.x, shift.x), 0.f);
        acc.y = fmaxf(fmaf(hv.y, scale.y, shift.y), 0.f);
        acc.z = fmaxf(fmaf(hv.z, scale.z, shift.z), 0.f);
        acc.w = fmaxf(fmaf(hv.w, scale.w, shift.w), 0.f);
    } else {
        acc = hv;
    }
    {
        float4 bt = *(const float4*)&s_bt[27 * 128 + lane * 4];
        acc.x += bt.x; acc.y += bt.y; acc.z += bt.z; acc.w += bt.w;
    }

    int beg = g_rowptr[n];
    int end = g_rowptr[n + 1];
    #pragma unroll 4
    for (int k = beg; k < end; k++) {
        uint32_t v = g_pack[k];
        int s = (int)(v & 0x07FFFFFFu);
        int code = (int)(v >> 27);
        float4 xv = h4[(size_t)s * 32 + lane];
        float4 bt = *(const float4*)&s_bt[code * 128 + lane * 4];
        if (doBN) {
            xv.x = fmaxf(fmaf(xv.x, scale.x, shift.x), 0.f);
            xv.y = fmaxf(fmaf(xv.y, scale.y, shift.y), 0.f);
            xv.z = fmaxf(fmaf(xv.z, scale.z, shift.z), 0.f);
            xv.w = fmaxf(fmaf(xv.w, scale.w, shift.w), 0.f);
        }
        acc.x += xv.x + bt.x;
        acc.y += xv.y + bt.y;
        acc.z += xv.z + bt.z;
        acc.w += xv.w + bt.w;
    }

    __half hh[4], hl[4];
    float* av = (float*)&acc;
    #pragma unroll
    for (int q = 0; q < 4; q++) {
        __half hi = __float2half_rn(av[q]);
        hh[q] = hi;
        hl[q] = __float2half_rn(av[q] - __half2float(hi));
    }
    *(uint2*)&g_ah[(size_t)n * D + lane * 4] = *(uint2*)hh;
    *(uint2*)&g_al[(size_t)n * D + lane * 4] = *(uint2*)hl;
}

// ---------------- shared GEMM helpers ----------------
#define SM_PITCH 72  // halves per row: 64 + 8 pad (144B, conflict-free)

__device__ __forceinline__ uint32_t smem_u32(const void* p) {
    uint32_t a;
    asm("{ .reg .u64 t; cvta.to.shared.u64 t, %1; cvt.u32.u64 %0, t; }"
        : "=r"(a) : "l"(p));
    return a;
}

__device__ __forceinline__ void ldmx4(uint32_t* r, uint32_t addr) {
    asm volatile("ldmatrix.sync.aligned.m8n8.x4.shared.b16 {%0,%1,%2,%3}, [%4];"
                 : "=r"(r[0]), "=r"(r[1]), "=r"(r[2]), "=r"(r[3]) : "r"(addr));
}

__device__ __forceinline__ void mma16816(float* c, const uint32_t* a,
                                         const uint32_t* b) {
    asm volatile(
        "mma.sync.aligned.m16n8k16.row.col.f32.f16.f16.f32 "
        "{%0,%1,%2,%3}, {%4,%5,%6,%7}, {%8,%9}, {%0,%1,%2,%3};"
        : "+f"(c[0]), "+f"(c[1]), "+f"(c[2]), "+f"(c[3])
        : "r"(a[0]), "r"(a[1]), "r"(a[2]), "r"(a[3]), "r"(b[0]), "r"(b[1]));
}

// ---------------- GEMM1: tile 128x64, 3 CTAs/SM (measured 44.4us) ---------
// hidden = relu(agg @ W1 + b1), split fp16 out.
__global__ void __launch_bounds__(256, 3)
mma_gemm1(const __half* __restrict__ Ah_g,
          const __half* __restrict__ Al_g,
          const __half* __restrict__ Wh_g,
          const __half* __restrict__ Wl_g,
          const float* __restrict__ bias,
          __half* __restrict__ Oh,
          __half* __restrict__ Ol,
          int M, int K, int Nc) {
    extern __shared__ __align__(16) char smem[];
    const int SZA = 128 * SM_PITCH * 2;
    const int SZB = 64 * SM_PITCH * 2;
    char* pAh = smem;
    char* pAl = smem + SZA;
    char* pBh = smem + 2 * SZA;
    char* pBl = smem + 2 * SZA + SZB;
    uint32_t sAh = smem_u32(pAh), sAl = sAh + SZA, sBh = sAh + 2 * SZA,
             sBl = sAh + 2 * SZA + SZB;

    int tid = threadIdx.x;
    int lane = tid & 31, w = tid >> 5;
    int wm = (w & 3) * 32;
    int wn = (w >> 2) * 32;
    int m0 = blockIdx.x * 128;
    int n0 = blockIdx.y * 64;

    float acc[2][4][4];
    #pragma unroll
    for (int i = 0; i < 2; i++)
        #pragma unroll
        for (int j = 0; j < 4; j++)
            #pragma unroll
            for (int q = 0; q < 4; q++) acc[i][j][q] = 0.f;

    const int nchunk = K / 64;
    for (int c = 0; c < nchunk; c++) {
        if (c > 0) __syncthreads();
        int k0 = c * 64;

        #pragma unroll
        for (int it = 0; it < 4; it++) {
            int idx = tid + it * 256;
            int r = idx >> 3, q = idx & 7;
            uint4 vh = make_uint4(0, 0, 0, 0), vl = vh;
            if (m0 + r < M) {
                size_t gi = (size_t)(m0 + r) * K + k0 + q * 8;
                vh = *(const uint4*)(Ah_g + gi);
                vl = *(const uint4*)(Al_g + gi);
            }
            int boff = (r * SM_PITCH + q * 8) * 2;
            *(uint4*)(pAh + boff) = vh;
            *(uint4*)(pAl + boff) = vl;
        }
        #pragma unroll
        for (int it = 0; it < 2; it++) {
            int idx = tid + it * 256;
            int n = idx >> 3, q = idx & 7;
            size_t gi = (size_t)(n0 + n) * K + k0 + q * 8;
            int boff = (n * SM_PITCH + q * 8) * 2;
            *(uint4*)(pBh + boff) = *(const uint4*)(Wh_g + gi);
            *(uint4*)(pBl + boff) = *(const uint4*)(Wl_g + gi);
        }
        __syncthreads();

        #pragma unroll
        for (int ks = 0; ks < 4; ks++) {
            uint32_t aH[2][4], aL[2][4], bH[4][2], bL[4][2];
            int arow = wm + (lane & 15);
            int acol = ks * 16 + (lane >> 4) * 8;
            #pragma unroll
            for (int i = 0; i < 2; i++) {
                uint32_t off = (uint32_t)(((arow + i * 16) * SM_PITCH + acol) * 2);
                ldmx4(aH[i], sAh + off);
                ldmx4(aL[i], sAl + off);
            }
            int brow = wn + ((lane >> 4) << 3) + (lane & 7);
            int bcol = ks * 16 + ((lane >> 3) & 1) * 8;
            #pragma unroll
            for (int p = 0; p < 2; p++) {
                uint32_t off = (uint32_t)(((brow + p * 16) * SM_PITCH + bcol) * 2);
                uint32_t t[4];
                ldmx4(t, sBh + off);
                bH[2 * p][0] = t[0]; bH[2 * p][1] = t[1];
                bH[2 * p + 1][0] = t[2]; bH[2 * p + 1][1] = t[3];
                ldmx4(t, sBl + off);
                bL[2 * p][0] = t[0]; bL[2 * p][1] = t[1];
                bL[2 * p + 1][0] = t[2]; bL[2 * p + 1][1] = t[3];
            }
            #pragma unroll
            for (int i = 0; i < 2; i++)
                #pragma unroll
                for (int j = 0; j < 4; j++) {
                    mma16816(acc[i][j], aH[i], bH[j]);
                    mma16816(acc[i][j], aL[i], bH[j]);
                    mma16816(acc[i][j], aH[i], bL[j]);
                }
        }
    }

    #pragma unroll
    for (int j = 0; j < 4; j++) {
        int col = n0 + wn + j * 8 + (lane & 3) * 2;
        float bx = __ldg(&bias[col]);
        float by = __ldg(&bias[col + 1]);
        #pragma unroll
        for (int i = 0; i < 2; i++) {
            int r0 = m0 + wm + i * 16 + (lane >> 2);
            float v0 = fmaxf(acc[i][j][0] + bx, 0.f);
            float v1 = fmaxf(acc[i][j][1] + by, 0.f);
            float v2 = fmaxf(acc[i][j][2] + bx, 0.f);
            float v3 = fmaxf(acc[i][j][3] + by, 0.f);
            __half h0 = __float2half_rn(v0), h1 = __float2half_rn(v1);
            __half h2 = __float2half_rn(v2), h3 = __float2half_rn(v3);
            __half l0 = __float2half_rn(v0 - __half2float(h0));
            __half l1 = __float2half_rn(v1 - __half2float(h1));
            __half l2 = __float2half_rn(v2 - __half2float(h2));
            __half l3 = __float2half_rn(v3 - __half2float(h3));
            if (r0 < M) {
                __half ph[2] = {h0, h1}, pl[2] = {l0, l1};
                *(uint32_t*)&Oh[(size_t)r0 * Nc + col] = *(uint32_t*)ph;
                *(uint32_t*)&Ol[(size_t)r0 * Nc + col] = *(uint32_t*)pl;
            }
            if (r0 + 8 < M) {
                __half ph[2] = {h2, h3}, pl[2] = {l2, l3};
                *(uint32_t*)&Oh[(size_t)(r0 + 8) * Nc + col] = *(uint32_t*)ph;
                *(uint32_t*)&Ol[(size_t)(r0 + 8) * Nc + col] = *(uint32_t*)pl;
            }
        }
    }
}

// ---------------- GEMM2: tile 64x128, 3 CTAs/SM (tail-wave fix) -----------
// h2 = hidden @ W2 + b2 (fp32) + fused BN stats.
// 8 warps: 2 along m (wm 0/32), 4 along n (wn 0..96). Warp tile 32x32.
__global__ void __launch_bounds__(256, 3)
mma_gemm2(const __half* __restrict__ Ah_g,
          const __half* __restrict__ Al_g,
          const __half* __restrict__ Wh_g,
          const __half* __restrict__ Wl_g,
          const float* __restrict__ bias,
          float* __restrict__ C,
          float* __restrict__ bnstat,
          int M, int K, int Nc) {
    extern __shared__ __align__(16) char smem[];
    const int SZA = 64 * SM_PITCH * 2;    // 9216
    const int SZB = 128 * SM_PITCH * 2;   // 18432
    char* pAh = smem;
    char* pAl = smem + SZA;
    char* pBh = smem + 2 * SZA;
    char* pBl = smem + 2 * SZA + SZB;
    uint32_t sAh = smem_u32(pAh), sAl = sAh + SZA, sBh = sAh + 2 * SZA,
             sBl = sAh + 2 * SZA + SZB;

    int tid = threadIdx.x;
    int lane = tid & 31, w = tid >> 5;
    int wm = (w & 1) * 32;     // 2 warps along m
    int wn = (w >> 1) * 32;    // 4 warps along n (covers full Nc=128)
    int m0 = blockIdx.x * 64;

    float acc[2][4][4];
    #pragma unroll
    for (int i = 0; i < 2; i++)
        #pragma unroll
        for (int j = 0; j < 4; j++)
            #pragma unroll
            for (int q = 0; q < 4; q++) acc[i][j][q] = 0.f;

    const int nchunk = K / 64;
    for (int c = 0; c < nchunk; c++) {
        if (c > 0) __syncthreads();
        int k0 = c * 64;

        // A: 64 rows x 64 halves = 512 16B-chunks per half, 2 iters
        #pragma unroll
        for (int it = 0; it < 2; it++) {
            int idx = tid + it * 256;
            int r = idx >> 3, q = idx & 7;
            uint4 vh = make_uint4(0, 0, 0, 0), vl = vh;
            if (m0 + r < M) {
                size_t gi = (size_t)(m0 + r) * K + k0 + q * 8;
                vh = *(const uint4*)(Ah_g + gi);
                vl = *(const uint4*)(Al_g + gi);
            }
            int boff = (r * SM_PITCH + q * 8) * 2;
            *(uint4*)(pAh + boff) = vh;
            *(uint4*)(pAl + boff) = vl;
        }
        // B: 128 n-rows x 64 halves = 1024 chunks per half, 4 iters
        #pragma unroll
        for (int it = 0; it < 4; it++) {
            int idx = tid + it * 256;
            int n = idx >> 3, q = idx & 7;
            size_t gi = (size_t)n * K + k0 + q * 8;
            int boff = (n * SM_PITCH + q * 8) * 2;
            *(uint4*)(pBh + boff) = *(const uint4*)(Wh_g + gi);
            *(uint4*)(pBl + boff) = *(const uint4*)(Wl_g + gi);
        }
        __syncthreads();

        #pragma unroll
        for (int ks = 0; ks < 4; ks++) {
            uint32_t aH[2][4], aL[2][4], bH[4][2], bL[4][2];
            int arow = wm + (lane & 15);
            int acol = ks * 16 + (lane >> 4) * 8;
            #pragma unroll
            for (int i = 0; i < 2; i++) {
                uint32_t off = (uint32_t)(((arow + i * 16) * SM_PITCH + acol) * 2);
                ldmx4(aH[i], sAh + off);
                ldmx4(aL[i], sAl + off);
            }
            int brow = wn + ((lane >> 4) << 3) + (lane & 7);
            int bcol = ks * 16 + ((lane >> 3) & 1) * 8;
            #pragma unroll
            for (int p = 0; p < 2; p++) {
                uint32_t off = (uint32_t)(((brow + p * 16) * SM_PITCH + bcol) * 2);
                uint32_t t[4];
                ldmx4(t, sBh + off);
                bH[2 * p][0] = t[0]; bH[2 * p][1] = t[1];
                bH[2 * p + 1][0] = t[2]; bH[2 * p + 1][1] = t[3];
                ldmx4(t, sBl + off);
                bL[2 * p][0] = t[0]; bL[2 * p][1] = t[1];
                bL[2 * p + 1][0] = t[2]; bL[2 * p + 1][1] = t[3];
            }
            #pragma unroll
            for (int i = 0; i < 2; i++)
                #pragma unroll
                for (int j = 0; j < 4; j++) {
                    mma16816(acc[i][j], aH[i], bH[j]);
                    mma16816(acc[i][j], aL[i], bH[j]);
                    mma16816(acc[i][j], aH[i], bL[j]);
                }
        }
    }

    #pragma unroll
    for (int j = 0; j < 4; j++) {
        int col = wn + j * 8 + (lane & 3) * 2;
        float bx = __ldg(&bias[col]);
        float by = __ldg(&bias[col + 1]);
        float s0 = 0.f, s1 = 0.f, q0 = 0.f, q1 = 0.f;
        #pragma unroll
        for (int i = 0; i < 2; i++) {
            int r0 = m0 + wm + i * 16 + (lane >> 2);
            float v0 = acc[i][j][0] + bx, v1 = acc[i][j][1] + by;
            float v2 = acc[i][j][2] + bx, v3 = acc[i][j][3] + by;
            if (r0 < M) {
                *(float2*)&C[(size_t)r0 * Nc + col] = make_float2(v0, v1);
                s0 += v0; s1 += v1; q0 += v0 * v0; q1 += v1 * v1;
            }
            if (r0 + 8 < M) {
                *(float2*)&C[(size_t)(r0 + 8) * Nc + col] = make_float2(v2, v3);
                s0 += v2; s1 += v3; q0 += v2 * v2; q1 += v3 * v3;
            }
        }
        #pragma unroll
        for (int d = 4; d < 32; d <<= 1) {
            s0 += __shfl_xor_sync(0xffffffff, s0, d);
            s1 += __shfl_xor_sync(0xffffffff, s1, d);
            q0 += __shfl_xor_sync(0xffffffff, q0, d);
            q1 += __shfl_xor_sync(0xffffffff, q1, d);
        }
        if (lane < 4) {
            atomicAdd(&bnstat[col], s0);
            atomicAdd(&bnstat[col + 1], s1);
            atomicAdd(&bnstat[128 + col], q0);
            atomicAdd(&bnstat[128 + col + 1], q1);
        }
    }
}

// ---------------- final BN apply (layer 4, no relu) ----------------
__global__ void k_bn_apply(float* __restrict__ dst,
                           const float* __restrict__ stat,
                           const float* __restrict__ gamma,
                           const float* __restrict__ beta, int N) {
    int idx = blockIdx.x * blockDim.x + threadIdx.x;
    if (idx >= N * D) return;
    int c = idx & (D - 1);
    float invN = 1.0f / (float)N;
    float mu = stat[c] * invN;
    float var = stat[128 + c] * invN - mu * mu;
    float istd = rsqrtf(var + 1e-5f);
    dst[idx] = (g_h2[idx] - mu) * istd * gamma[c] + beta[c];
}

// ---------------- launch ----------------
extern "C" void kernel_launch(void* const* d_in, const int* in_sizes, int n_in,
                              void* d_out, int out_size) {
    const int*   x     = (const int*)d_in[0];
    const int*   ei    = (const int*)d_in[1];
    const int*   ea    = (const int*)d_in[2];
    const float* ae1   = (const float*)d_in[3];
    const float* ae2   = (const float*)d_in[4];
    const float* be1   = (const float*)d_in[5];
    const float* be2   = (const float*)d_in[6];
    const float* W1    = (const float*)d_in[7];
    const float* b1    = (const float*)d_in[8];
    const float* W2    = (const float*)d_in[9];
    const float* b2    = (const float*)d_in[10];
    const float* gamma = (const float*)d_in[11];
    const float* beta  = (const float*)d_in[12];

    int N = in_sizes[0] / 2;
    int E = in_sizes[1] / 2;

    float *p_h, *p_h2, *p_bn;
    int *p_deg, *p_flag1, *p_flag2;
    __half *p_ah, *p_al, *p_hh, *p_hl, *p_w1h, *p_w1l, *p_w2h, *p_w2l;
    cudaGetSymbolAddress((void**)&p_h, g_h);
    cudaGetSymbolAddress((void**)&p_h2, g_h2);
    cudaGetSymbolAddress((void**)&p_bn, g_bnstat);
    cudaGetSymbolAddress((void**)&p_deg, g_deg);
    cudaGetSymbolAddress((void**)&p_flag1, g_flag1);
    cudaGetSymbolAddress((void**)&p_flag2, g_flag2);
    cudaGetSymbolAddress((void**)&p_ah, g_ah);
    cudaGetSymbolAddress((void**)&p_al, g_al);
    cudaGetSymbolAddress((void**)&p_hh, g_hh);
    cudaGetSymbolAddress((void**)&p_hl, g_hl);
    cudaGetSymbolAddress((void**)&p_w1h, g_w1h);
    cudaGetSymbolAddress((void**)&p_w1l, g_w1l);
    cudaGetSymbolAddress((void**)&p_w2h, g_w2h);
    cudaGetSymbolAddress((void**)&p_w2l, g_w2l);

    const int SMEM1 = 2 * 128 * SM_PITCH * 2 + 2 * 64 * SM_PITCH * 2;  // 55296
    const int SMEM2 = 2 * 64 * SM_PITCH * 2 + 2 * 128 * SM_PITCH * 2;  // 55296
    cudaFuncSetAttribute(mma_gemm1,
                         cudaFuncAttributeMaxDynamicSharedMemorySize, SMEM1);
    cudaFuncSetAttribute(mma_gemm2,
                         cudaFuncAttributeMaxDynamicSharedMemorySize, SMEM2);

    cudaMemsetAsync(p_deg, 0, (size_t)N * sizeof(int));
    cudaMemsetAsync(p_flag1, 0, 256 * sizeof(int));
    cudaMemsetAsync(p_flag2, 0, 256 * sizeof(int));

    int nbE = (E + 255) / 256;
    int nbAtom = (N * D + 255) / 256;
    int nbPrep = (NLAYER * 256 * 128 + 255) / 256;
    int nb = (N + 255) / 256;

    k_init<<<nbE + nbAtom + nbPrep, 256>>>(ei, x, ae1, ae2, W1, W2,
                                           N, E, nbE, nbAtom);
    k_scanfill<<<nb, 256>>>(ei, ea, N, E);

    int mtiles = (N + 127) / 128;
    int mtiles64 = (N + 63) / 64;

    for (int l = 0; l < NLAYER; l++) {
        const float* be1L = be1 + (size_t)l * 7 * D;
        const float* be2L = be2 + (size_t)l * 4 * D;
        float* bn_cur  = p_bn + (l & 1) * 256;
        float* bn_prev = p_bn + ((l - 1) & 1) * 256;

        int totalThreads = N * 32;
        k_aggregate<<<(totalThreads + 255) / 256, 256>>>(
            be1L, be2L,
            (l == 0) ? p_h : p_h2,
            bn_prev, bn_cur,
            gamma + (size_t)(l > 0 ? l - 1 : 0) * D,
            beta + (size_t)(l > 0 ? l - 1 : 0) * D,
            N, l > 0);

        // GEMM1 (profiled at l==0 as launch #4): 128x64 tile, 3 CTA/SM
        dim3 g1(mtiles, 4);
        mma_gemm1<<<g1, 256, SMEM1>>>(
            p_ah, p_al, p_w1h + (size_t)l * 32768, p_w1l + (size_t)l * 32768,
            b1 + (size_t)l * 256, p_hh, p_hl, N, 128, 256);

        // GEMM2: 64x128 tile, 3 CTA/SM (tail-wave fix)
        mma_gemm2<<<mtiles64, 256, SMEM2>>>(
            p_hh, p_hl, p_w2h + (size_t)l * 32768, p_w2l + (size_t)l * 32768,
            b2 + (size_t)l * 128, p_h2, bn_cur, N, 256, 128);
    }

    k_bn_apply<<<((size_t)N * D + 255) / 256, 256>>>(
        (float*)d_out, p_bn + (4 & 1) * 256,
        gamma + (size_t)4 * D, beta + (size_t)4 * D, N);
}

// round 16
// speedup vs baseline: 1.0791x; 1.0791x over previous
#include <cuda_runtime.h>
#include <cuda_fp16.h>
#include <cstdint>

#define D 128
#define MAXN 65536
#define MAXE 1048576
#define NLAYER 5

// ---------------- static scratch ----------------
__device__ float    g_h[(size_t)MAXN * D];
__device__ float    g_h2[(size_t)MAXN * D];
__device__ __half   g_ah[(size_t)MAXN * D];
__device__ __half   g_al[(size_t)MAXN * D];
__device__ __half   g_hh[(size_t)MAXN * 2 * D];
__device__ __half   g_hl[(size_t)MAXN * 2 * D];
__device__ int      g_deg[MAXN];
__device__ int      g_rowptr[MAXN + 1];
__device__ int      g_cursor[MAXN];
__device__ uint32_t g_pack[MAXE];
__device__ int      g_bsum[256];
__device__ int      g_flag1[256];
__device__ int      g_flag2[256];
__device__ float    g_bnstat[2][256];
__device__ __half   g_w1h[NLAYER * 256 * 128];
__device__ __half   g_w1l[NLAYER * 256 * 128];
__device__ __half   g_w2h[NLAYER * 128 * 256];
__device__ __half   g_w2l[NLAYER * 128 * 256];

// ---------------- fused init: edge count | atom encoder | weight prep ------
__global__ void __launch_bounds__(256)
k_init(const int* __restrict__ ei,
       const int* __restrict__ x,
       const float* __restrict__ ae1,
       const float* __restrict__ ae2,
       const float* __restrict__ W1,
       const float* __restrict__ W2,
       int N, int E, int nbE, int nbAtom) {
    int b = blockIdx.x;
    if (b < nbE) {
        int e = b * 256 + threadIdx.x;
        if (e < E) atomicAdd(&g_deg[ei[E + e]], 1);
    } else if (b < nbE + nbAtom) {
        int idx = (b - nbE) * 256 + threadIdx.x;
        if (idx < N * D) {
            int n = idx >> 7, d = idx & (D - 1);
            g_h[idx] = ae1[x[2 * n] * D + d] + ae2[x[2 * n + 1] * D + d];
        }
    } else {
        int idx = (b - nbE - nbAtom) * 256 + threadIdx.x;
        if (idx < NLAYER * 256 * 128) {
            int l = idx >> 15;
            int r = idx & 32767;
            {
                int n = r >> 7, k = r & 127;
                float v = W1[(size_t)l * 32768 + (size_t)k * 256 + n];
                __half h = __float2half_rn(v);
                g_w1h[idx] = h;
                g_w1l[idx] = __float2half_rn(v - __half2float(h));
            }
            {
                int n = r >> 8, k = r & 255;
                float v = W2[(size_t)l * 32768 + (size_t)k * 128 + n];
                __half h = __float2half_rn(v);
                g_w2h[idx] = h;
                g_w2l[idx] = __float2half_rn(v - __half2float(h));
            }
        }
    }
}

// ---------------- fused CSR: scan (decoupled lookback) + packed fill -------
__global__ void __launch_bounds__(256)
k_scanfill(const int* __restrict__ ei, const int* __restrict__ ea,
           int N, int E) {
    int b = blockIdx.x, tid = threadIdx.x;
    int nb = gridDim.x;
    __shared__ int s[256];
    __shared__ int spre[256];

    int i = b * 256 + tid;
    int v = (i < N) ? g_deg[i] : 0;
    s[tid] = v;
    __syncthreads();
    #pragma unroll
    for (int off = 1; off < 256; off <<= 1) {
        int t = (tid >= off) ? s[tid - off] : 0;
        __syncthreads();
        s[tid] += t;
        __syncthreads();
    }
    if (tid == 0) {
        g_bsum[b] = s[255];
        __threadfence();
        atomicExch(&g_flag1[b], 1);
    }

    int part = 0;
    if (tid < b) {
        while (atomicAdd(&g_flag1[tid], 0) == 0) {}
        part = atomicAdd(&g_bsum[tid], 0);
    }
    spre[tid] = part;
    __syncthreads();
    #pragma unroll
    for (int off = 128; off > 0; off >>= 1) {
        if (tid < off) spre[tid] += spre[tid + off];
        __syncthreads();
    }
    int prefix = spre[0];

    if (i < N) {
        int r = prefix + s[tid] - v;
        g_rowptr[i] = r;
        g_cursor[i] = r;
    }
    if (i == 0) g_rowptr[N] = E;
    __threadfence();
    __syncthreads();
    if (tid == 0) atomicExch(&g_flag2[b], 1);

    if (tid < nb) {
        while (atomicAdd(&g_flag2[tid], 0) == 0) {}
    }
    __syncthreads();
    __threadfence();

    for (int e = b * 256 + tid; e < E; e += nb * 256) {
        int dst = ei[E + e];
        int src = ei[e];
        uint32_t code = (uint32_t)(ea[2 * e] * 4 + ea[2 * e + 1]);
        int pos = atomicAdd(&g_cursor[dst], 1);
        g_pack[pos] = (uint32_t)src | (code << 27);
    }
}

// ---------------- aggregation (identical to R9) ----------------
__global__ void __launch_bounds__(256)
k_aggregate(const float* __restrict__ be1,
            const float* __restrict__ be2,
            const float* __restrict__ srcfeat,
            const float* __restrict__ bnstat_prev,
            float* __restrict__ bnstat_cur,
            const float* __restrict__ gammaP,
            const float* __restrict__ betaP,
            int N, int doBN) {
    __shared__ float s_bt[28 * 128];
    for (int idx = threadIdx.x; idx < 28 * 128; idx += 256) {
        int c = idx >> 7, d = idx & 127;
        s_bt[idx] = be1[(c >> 2) * 128 + d] + be2[(c & 3) * 128 + d];
    }
    if (blockIdx.x == 0 && threadIdx.x < 256) bnstat_cur[threadIdx.x] = 0.f;
    __syncthreads();

    int gw = (blockIdx.x * blockDim.x + threadIdx.x) >> 5;
    int lane = threadIdx.x & 31;
    if (gw >= N) return;
    int n = gw;

    float4 scale = make_float4(1.f, 1.f, 1.f, 1.f);
    float4 shift = make_float4(0.f, 0.f, 0.f, 0.f);
    if (doBN) {
        float invN = 1.0f / (float)N;
        #pragma unroll
        for (int q = 0; q < 4; q++) {
            int c = lane * 4 + q;
            float mu = bnstat_prev[c] * invN;
            float var = bnstat_prev[128 + c] * invN - mu * mu;
            float istd = rsqrtf(var + 1e-5f);
            float sc = istd * gammaP[c];
            float sh = betaP[c] - mu * sc;
            ((float*)&scale)[q] = sc;
            ((float*)&shift)[q] = sh;
        }
    }

    const float4* h4 = (const float4*)srcfeat;

    float4 hv = h4[(size_t)n * 32 + lane];
    float4 acc;
    if (doBN) {
        acc.x = fmaxf(fmaf(hv.x, scale.x, shift.x), 0.f);
        acc.y = fmaxf(fmaf(hv.y, scale.y, shift.y), 0.f);
        acc.z = fmaxf(fmaf(hv.z, scale.z, shift.z), 0.f);
        acc.w = fmaxf(fmaf(hv.w, scale.w, shift.w), 0.f);
    } else {
        acc = hv;
    }
    {
        float4 bt = *(const float4*)&s_bt[27 * 128 + lane * 4];
        acc.x += bt.x; acc.y += bt.y; acc.z += bt.z; acc.w += bt.w;
    }

    int beg = g_rowptr[n];
    int end = g_rowptr[n + 1];
    #pragma unroll 4
    for (int k = beg; k < end; k++) {
        uint32_t v = g_pack[k];
        int s = (int)(v & 0x07FFFFFFu);
        int code = (int)(v >> 27);
        float4 xv = h4[(size_t)s * 32 + lane];
        float4 bt = *(const float4*)&s_bt[code * 128 + lane * 4];
        if (doBN) {
            xv.x = fmaxf(fmaf(xv.x, scale.x, shift.x), 0.f);
            xv.y = fmaxf(fmaf(xv.y, scale.y, shift.y), 0.f);
            xv.z = fmaxf(fmaf(xv.z, scale.z, shift.z), 0.f);
            xv.w = fmaxf(fmaf(xv.w, scale.w, shift.w), 0.f);
        }
        acc.x += xv.x + bt.x;
        acc.y += xv.y + bt.y;
        acc.z += xv.z + bt.z;
        acc.w += xv.w + bt.w;
    }

    __half hh[4], hl[4];
    float* av = (float*)&acc;
    #pragma unroll
    for (int q = 0; q < 4; q++) {
        __half hi = __float2half_rn(av[q]);
        hh[q] = hi;
        hl[q] = __float2half_rn(av[q] - __half2float(hi));
    }
    *(uint2*)&g_ah[(size_t)n * D + lane * 4] = *(uint2*)hh;
    *(uint2*)&g_al[(size_t)n * D + lane * 4] = *(uint2*)hl;
}

// ---------------- shared GEMM helpers ----------------
#define SM_PITCH 72  // halves per row: 64 + 8 pad (144B, conflict-free)

__device__ __forceinline__ uint32_t smem_u32(const void* p) {
    uint32_t a;
    asm("{ .reg .u64 t; cvta.to.shared.u64 t, %1; cvt.u32.u64 %0, t; }"
        : "=r"(a) : "l"(p));
    return a;
}

__device__ __forceinline__ void cp16(uint32_t saddr, const void* gptr, int srcsz) {
    asm volatile("cp.async.cg.shared.global [%0], [%1], 16, %2;"
                 :: "r"(saddr), "l"(__cvta_generic_to_global(gptr)), "r"(srcsz));
}

__device__ __forceinline__ void ldmx4(uint32_t* r, uint32_t addr) {
    asm volatile("ldmatrix.sync.aligned.m8n8.x4.shared.b16 {%0,%1,%2,%3}, [%4];"
                 : "=r"(r[0]), "=r"(r[1]), "=r"(r[2]), "=r"(r[3]) : "r"(addr));
}

__device__ __forceinline__ void mma16816(float* c, const uint32_t* a,
                                         const uint32_t* b) {
    asm volatile(
        "mma.sync.aligned.m16n8k16.row.col.f32.f16.f16.f32 "
        "{%0,%1,%2,%3}, {%4,%5,%6,%7}, {%8,%9}, {%0,%1,%2,%3};"
        : "+f"(c[0]), "+f"(c[1]), "+f"(c[2]), "+f"(c[3])
        : "r"(a[0]), "r"(a[1]), "r"(a[2]), "r"(a[3]), "r"(b[0]), "r"(b[1]));
}

// ---------------- GEMM1: tile 128x64, 3 CTAs/SM, cp.async staging ---------
// hidden = relu(agg @ W1 + b1), split fp16 out.
__global__ void __launch_bounds__(256, 3)
mma_gemm1(const __half* __restrict__ Ah_g,
          const __half* __restrict__ Al_g,
          const __half* __restrict__ Wh_g,
          const __half* __restrict__ Wl_g,
          const float* __restrict__ bias,
          __half* __restrict__ Oh,
          __half* __restrict__ Ol,
          int M, int K, int Nc) {
    extern __shared__ __align__(16) char smem[];
    const int SZA = 128 * SM_PITCH * 2;
    const int SZB = 64 * SM_PITCH * 2;
    uint32_t sAh = smem_u32(smem);
    uint32_t sAl = sAh + SZA;
    uint32_t sBh = sAh + 2 * SZA;
    uint32_t sBl = sAh + 2 * SZA + SZB;

    int tid = threadIdx.x;
    int lane = tid & 31, w = tid >> 5;
    int wm = (w & 3) * 32;
    int wn = (w >> 2) * 32;
    int m0 = blockIdx.x * 128;
    int n0 = blockIdx.y * 64;

    float acc[2][4][4];
    #pragma unroll
    for (int i = 0; i < 2; i++)
        #pragma unroll
        for (int j = 0; j < 4; j++)
            #pragma unroll
            for (int q = 0; q < 4; q++) acc[i][j][q] = 0.f;

    const int nchunk = K / 64;
    for (int c = 0; c < nchunk; c++) {
        if (c > 0) __syncthreads();
        int k0 = c * 64;

        #pragma unroll
        for (int it = 0; it < 4; it++) {
            int idx = tid + it * 256;
            int r = idx >> 3, q = idx & 7;
            int srcsz = (m0 + r < M) ? 16 : 0;
            size_t gi = (size_t)(m0 + r) * K + k0 + q * 8;
            uint32_t boff = (uint32_t)((r * SM_PITCH + q * 8) * 2);
            cp16(sAh + boff, Ah_g + gi, srcsz);
            cp16(sAl + boff, Al_g + gi, srcsz);
        }
        #pragma unroll
        for (int it = 0; it < 2; it++) {
            int idx = tid + it * 256;
            int n = idx >> 3, q = idx & 7;
            size_t gi = (size_t)(n0 + n) * K + k0 + q * 8;
            uint32_t boff = (uint32_t)((n * SM_PITCH + q * 8) * 2);
            cp16(sBh + boff, Wh_g + gi, 16);
            cp16(sBl + boff, Wl_g + gi, 16);
        }
        asm volatile("cp.async.commit_group;");
        asm volatile("cp.async.wait_group 0;");
        __syncthreads();

        #pragma unroll
        for (int ks = 0; ks < 4; ks++) {
            uint32_t aH[2][4], aL[2][4], bH[4][2], bL[4][2];
            int arow = wm + (lane & 15);
            int acol = ks * 16 + (lane >> 4) * 8;
            #pragma unroll
            for (int i = 0; i < 2; i++) {
                uint32_t off = (uint32_t)(((arow + i * 16) * SM_PITCH + acol) * 2);
                ldmx4(aH[i], sAh + off);
                ldmx4(aL[i], sAl + off);
            }
            int brow = wn + ((lane >> 4) << 3) + (lane & 7);
            int bcol = ks * 16 + ((lane >> 3) & 1) * 8;
            #pragma unroll
            for (int p = 0; p < 2; p++) {
                uint32_t off = (uint32_t)(((brow + p * 16) * SM_PITCH + bcol) * 2);
                uint32_t t[4];
                ldmx4(t, sBh + off);
                bH[2 * p][0] = t[0]; bH[2 * p][1] = t[1];
                bH[2 * p + 1][0] = t[2]; bH[2 * p + 1][1] = t[3];
                ldmx4(t, sBl + off);
                bL[2 * p][0] = t[0]; bL[2 * p][1] = t[1];
                bL[2 * p + 1][0] = t[2]; bL[2 * p + 1][1] = t[3];
            }
            #pragma unroll
            for (int i = 0; i < 2; i++)
                #pragma unroll
                for (int j = 0; j < 4; j++) {
                    mma16816(acc[i][j], aH[i], bH[j]);
                    mma16816(acc[i][j], aL[i], bH[j]);
                    mma16816(acc[i][j], aH[i], bL[j]);
                }
        }
    }

    #pragma unroll
    for (int j = 0; j < 4; j++) {
        int col = n0 + wn + j * 8 + (lane & 3) * 2;
        float bx = __ldg(&bias[col]);
        float by = __ldg(&bias[col + 1]);
        #pragma unroll
        for (int i = 0; i < 2; i++) {
            int r0 = m0 + wm + i * 16 + (lane >> 2);
            float v0 = fmaxf(acc[i][j][0] + bx, 0.f);
            float v1 = fmaxf(acc[i][j][1] + by, 0.f);
            float v2 = fmaxf(acc[i][j][2] + bx, 0.f);
            float v3 = fmaxf(acc[i][j][3] + by, 0.f);
            __half h0 = __float2half_rn(v0), h1 = __float2half_rn(v1);
            __half h2 = __float2half_rn(v2), h3 = __float2half_rn(v3);
            __half l0 = __float2half_rn(v0 - __half2float(h0));
            __half l1 = __float2half_rn(v1 - __half2float(h1));
            __half l2 = __float2half_rn(v2 - __half2float(h2));
            __half l3 = __float2half_rn(v3 - __half2float(h3));
            if (r0 < M) {
                __half ph[2] = {h0, h1}, pl[2] = {l0, l1};
                *(uint32_t*)&Oh[(size_t)r0 * Nc + col] = *(uint32_t*)ph;
                *(uint32_t*)&Ol[(size_t)r0 * Nc + col] = *(uint32_t*)pl;
            }
            if (r0 + 8 < M) {
                __half ph[2] = {h2, h3}, pl[2] = {l2, l3};
                *(uint32_t*)&Oh[(size_t)(r0 + 8) * Nc + col] = *(uint32_t*)ph;
                *(uint32_t*)&Ol[(size_t)(r0 + 8) * Nc + col] = *(uint32_t*)pl;
            }
        }
    }
}

// ---------------- GEMM2: tile 128x128, 2 CTAs/SM, cp.async staging --------
// h2 = hidden @ W2 + b2 (fp32) + fused BN stats.
__global__ void __launch_bounds__(256, 2)
mma_gemm2(const __half* __restrict__ Ah_g,
          const __half* __restrict__ Al_g,
          const __half* __restrict__ Wh_g,
          const __half* __restrict__ Wl_g,
          const float* __restrict__ bias,
          float* __restrict__ C,
          float* __restrict__ bnstat,
          int M, int K, int Nc) {
    extern __shared__ __align__(16) char smem[];
    const int SZ = 128 * SM_PITCH * 2;
    uint32_t sAh = smem_u32(smem);
    uint32_t sAl = sAh + SZ;
    uint32_t sBh = sAh + 2 * SZ;
    uint32_t sBl = sAh + 3 * SZ;

    int tid = threadIdx.x;
    int lane = tid & 31, w = tid >> 5;
    int wm = (w & 1) * 64;
    int wn = (w >> 1) * 32;
    int m0 = blockIdx.x * 128;
    int n0 = blockIdx.y * 128;

    float acc[4][4][4];
    #pragma unroll
    for (int i = 0; i < 4; i++)
        #pragma unroll
        for (int j = 0; j < 4; j++)
            #pragma unroll
            for (int q = 0; q < 4; q++) acc[i][j][q] = 0.f;

    const int nchunk = K / 64;
    for (int c = 0; c < nchunk; c++) {
        if (c > 0) __syncthreads();
        int k0 = c * 64;

        #pragma unroll
        for (int it = 0; it < 4; it++) {
            int idx = tid + it * 256;
            int r = idx >> 3, q = idx & 7;
            int srcsz = (m0 + r < M) ? 16 : 0;
            size_t gi = (size_t)(m0 + r) * K + k0 + q * 8;
            uint32_t boff = (uint32_t)((r * SM_PITCH + q * 8) * 2);
            cp16(sAh + boff, Ah_g + gi, srcsz);
            cp16(sAl + boff, Al_g + gi, srcsz);
        }
        #pragma unroll
        for (int it = 0; it < 4; it++) {
            int idx = tid + it * 256;
            int n = idx >> 3, q = idx & 7;
            size_t gi = (size_t)(n0 + n) * K + k0 + q * 8;
            uint32_t boff = (uint32_t)((n * SM_PITCH + q * 8) * 2);
            cp16(sBh + boff, Wh_g + gi, 16);
            cp16(sBl + boff, Wl_g + gi, 16);
        }
        asm volatile("cp.async.commit_group;");
        asm volatile("cp.async.wait_group 0;");
        __syncthreads();

        #pragma unroll
        for (int ks = 0; ks < 4; ks++) {
            uint32_t aH[4][4], aL[4][4], bH[4][2], bL[4][2];
            int arow = wm + (lane & 15);
            int acol = ks * 16 + (lane >> 4) * 8;
            #pragma unroll
            for (int i = 0; i < 4; i++) {
                uint32_t off = (uint32_t)(((arow + i * 16) * SM_PITCH + acol) * 2);
                ldmx4(aH[i], sAh + off);
                ldmx4(aL[i], sAl + off);
            }
            int brow = wn + ((lane >> 4) << 3) + (lane & 7);
            int bcol = ks * 16 + ((lane >> 3) & 1) * 8;
            #pragma unroll
            for (int p = 0; p < 2; p++) {
                uint32_t off = (uint32_t)(((brow + p * 16) * SM_PITCH + bcol) * 2);
                uint32_t t[4];
                ldmx4(t, sBh + off);
                bH[2 * p][0] = t[0]; bH[2 * p][1] = t[1];
                bH[2 * p + 1][0] = t[2]; bH[2 * p + 1][1] = t[3];
                ldmx4(t, sBl + off);
                bL[2 * p][0] = t[0]; bL[2 * p][1] = t[1];
                bL[2 * p + 1][0] = t[2]; bL[2 * p + 1][1] = t[3];
            }
            #pragma unroll
            for (int i = 0; i < 4; i++)
                #pragma unroll
                for (int j = 0; j < 4; j++) {
                    mma16816(acc[i][j], aH[i], bH[j]);
                    mma16816(acc[i][j], aL[i], bH[j]);
                    mma16816(acc[i][j], aH[i], bL[j]);
                }
        }
    }

    #pragma unroll
    for (int j = 0; j < 4; j++) {
        int col = n0 + wn + j * 8 + (lane & 3) * 2;
        float bx = __ldg(&bias[col]);
        float by = __ldg(&bias[col + 1]);
        float s0 = 0.f, s1 = 0.f, q0 = 0.f, q1 = 0.f;
        #pragma unroll
        for (int i = 0; i < 4; i++) {
            int r0 = m0 + wm + i * 16 + (lane >> 2);
            float v0 = acc[i][j][0] + bx, v1 = acc[i][j][1] + by;
            float v2 = acc[i][j][2] + bx, v3 = acc[i][j][3] + by;
            if (r0 < M) {
                *(float2*)&C[(size_t)r0 * Nc + col] = make_float2(v0, v1);
                s0 += v0; s1 += v1; q0 += v0 * v0; q1 += v1 * v1;
            }
            if (r0 + 8 < M) {
                *(float2*)&C[(size_t)(r0 + 8) * Nc + col] = make_float2(v2, v3);
                s0 += v2; s1 += v3; q0 += v2 * v2; q1 += v3 * v3;
            }
        }
        #pragma unroll
        for (int d = 4; d < 32; d <<= 1) {
            s0 += __shfl_xor_sync(0xffffffff, s0, d);
            s1 += __shfl_xor_sync(0xffffffff, s1, d);
            q0 += __shfl_xor_sync(0xffffffff, q0, d);
            q1 += __shfl_xor_sync(0xffffffff, q1, d);
        }
        if (lane < 4) {
            atomicAdd(&bnstat[col], s0);
            atomicAdd(&bnstat[col + 1], s1);
            atomicAdd(&bnstat[128 + col], q0);
            atomicAdd(&bnstat[128 + col + 1], q1);
        }
    }
}

// ---------------- final BN apply (layer 4, no relu) ----------------
__global__ void k_bn_apply(float* __restrict__ dst,
                           const float* __restrict__ stat,
                           const float* __restrict__ gamma,
                           const float* __restrict__ beta, int N) {
    int idx = blockIdx.x * blockDim.x + threadIdx.x;
    if (idx >= N * D) return;
    int c = idx & (D - 1);
    float invN = 1.0f / (float)N;
    float mu = stat[c] * invN;
    float var = stat[128 + c] * invN - mu * mu;
    float istd = rsqrtf(var + 1e-5f);
    dst[idx] = (g_h2[idx] - mu) * istd * gamma[c] + beta[c];
}

// ---------------- launch ----------------
extern "C" void kernel_launch(void* const* d_in, const int* in_sizes, int n_in,
                              void* d_out, int out_size) {
    const int*   x     = (const int*)d_in[0];
    const int*   ei    = (const int*)d_in[1];
    const int*   ea    = (const int*)d_in[2];
    const float* ae1   = (const float*)d_in[3];
    const float* ae2   = (const float*)d_in[4];
    const float* be1   = (const float*)d_in[5];
    const float* be2   = (const float*)d_in[6];
    const float* W1    = (const float*)d_in[7];
    const float* b1    = (const float*)d_in[8];
    const float* W2    = (const float*)d_in[9];
    const float* b2    = (const float*)d_in[10];
    const float* gamma = (const float*)d_in[11];
    const float* beta  = (const float*)d_in[12];

    int N = in_sizes[0] / 2;
    int E = in_sizes[1] / 2;

    float *p_h, *p_h2, *p_bn;
    int *p_deg, *p_flag1, *p_flag2;
    __half *p_ah, *p_al, *p_hh, *p_hl, *p_w1h, *p_w1l, *p_w2h, *p_w2l;
    cudaGetSymbolAddress((void**)&p_h, g_h);
    cudaGetSymbolAddress((void**)&p_h2, g_h2);
    cudaGetSymbolAddress((void**)&p_bn, g_bnstat);
    cudaGetSymbolAddress((void**)&p_deg, g_deg);
    cudaGetSymbolAddress((void**)&p_flag1, g_flag1);
    cudaGetSymbolAddress((void**)&p_flag2, g_flag2);
    cudaGetSymbolAddress((void**)&p_ah, g_ah);
    cudaGetSymbolAddress((void**)&p_al, g_al);
    cudaGetSymbolAddress((void**)&p_hh, g_hh);
    cudaGetSymbolAddress((void**)&p_hl, g_hl);
    cudaGetSymbolAddress((void**)&p_w1h, g_w1h);
    cudaGetSymbolAddress((void**)&p_w1l, g_w1l);
    cudaGetSymbolAddress((void**)&p_w2h, g_w2h);
    cudaGetSymbolAddress((void**)&p_w2l, g_w2l);

    const int SMEM1 = 2 * 128 * SM_PITCH * 2 + 2 * 64 * SM_PITCH * 2;  // 55296
    const int SMEM2 = 4 * 128 * SM_PITCH * 2;                          // 73728
    cudaFuncSetAttribute(mma_gemm1,
                         cudaFuncAttributeMaxDynamicSharedMemorySize, SMEM1);
    cudaFuncSetAttribute(mma_gemm2,
                         cudaFuncAttributeMaxDynamicSharedMemorySize, SMEM2);

    cudaMemsetAsync(p_deg, 0, (size_t)N * sizeof(int));
    cudaMemsetAsync(p_flag1, 0, 256 * sizeof(int));
    cudaMemsetAsync(p_flag2, 0, 256 * sizeof(int));

    int nbE = (E + 255) / 256;
    int nbAtom = (N * D + 255) / 256;
    int nbPrep = (NLAYER * 256 * 128 + 255) / 256;
    int nb = (N + 255) / 256;

    k_init<<<nbE + nbAtom + nbPrep, 256>>>(ei, x, ae1, ae2, W1, W2,
                                           N, E, nbE, nbAtom);
    k_scanfill<<<nb, 256>>>(ei, ea, N, E);

    int mtiles = (N + 127) / 128;

    for (int l = 0; l < NLAYER; l++) {
        const float* be1L = be1 + (size_t)l * 7 * D;
        const float* be2L = be2 + (size_t)l * 4 * D;
        float* bn_cur  = p_bn + (l & 1) * 256;
        float* bn_prev = p_bn + ((l - 1) & 1) * 256;

        int totalThreads = N * 32;
        k_aggregate<<<(totalThreads + 255) / 256, 256>>>(
            be1L, be2L,
            (l == 0) ? p_h : p_h2,
            bn_prev, bn_cur,
            gamma + (size_t)(l > 0 ? l - 1 : 0) * D,
            beta + (size_t)(l > 0 ? l - 1 : 0) * D,
            N, l > 0);

        // GEMM1 (profiled at l==0 as launch #4): 128x64 tile, 3 CTA/SM
        dim3 g1(mtiles, 4);
        mma_gemm1<<<g1, 256, SMEM1>>>(
            p_ah, p_al, p_w1h + (size_t)l * 32768, p_w1l + (size_t)l * 32768,
            b1 + (size_t)l * 256, p_hh, p_hl, N, 128, 256);

        // GEMM2: 128x128 tile, 2 CTA/SM
        dim3 g2(mtiles, 1);
        mma_gemm2<<<g2, 256, SMEM2>>>(
            p_hh, p_hl, p_w2h + (size_t)l * 32768, p_w2l + (size_t)l * 32768,
            b2 + (size_t)l * 128, p_h2, bn_cur, N, 256, 128);
    }

    k_bn_apply<<<((size_t)N * D + 255) / 256, 256>>>(
        (float*)d_out, p_bn + (4 & 1) * 256,
        gamma + (size_t)4 * D, beta + (size_t)4 * D, N);
}